// round 2
// baseline (speedup 1.0000x reference)
#include <cuda_runtime.h>
#include <cuda_bf16.h>
#include <cstdint>

// Problem constants (from reference): E=8, OUT=4096, IN=1024, B=16, S=2048
#define NB   16
#define NS   2048
#define NIN  1024
#define NOUT 4096
#define NE   8

// Routing result lives in a device global (no allocations allowed).
__device__ int g_expert_idx[NB];

// ---------------------------------------------------------------------------
// Kernel 1: top-1 routing (argmax over E=8 probs per batch, first-max wins)
// Optionally writes expert indices (as float) into the tail of d_out, since
// the reference returns (x_out, expert_idx) as a tuple.
// ---------------------------------------------------------------------------
__global__ void route_kernel(const float* __restrict__ probs,
                             float* __restrict__ out_tail, int n_tail) {
    int b = threadIdx.x;
    if (b < NB) {
        const float* p = probs + b * NE;
        float best = p[0];
        int bi = 0;
#pragma unroll
        for (int e = 1; e < NE; e++) {
            float v = p[e];
            if (v > best) { best = v; bi = e; }
        }
        g_expert_idx[b] = bi;
        if (out_tail != nullptr && b < n_tail) {
            out_tail[b] = (float)bi;
        }
    }
}

// ---------------------------------------------------------------------------
// Kernel 2: per-batch GEMM  C[b] = x[b] @ W[e(b)]^T + bias[e(b)]
//   x : [B, S, IN]  row-major (A, K-major)
//   W : [E, OUT, IN] row-major (B, K-major)  -> C[m][n] = sum_k A[m][k]*W[n][k]
//   C : [B, S, OUT]
// Classic 128x128x16 register-blocked SGEMM, 256 threads, 8x8 per thread.
// ---------------------------------------------------------------------------
#define BM 128
#define BN 128
#define BK 16
#define TM 8
#define TN 8
// (BM/TM) * (BN/TN) = 16*16 = 256 threads

__global__ __launch_bounds__(256, 1)
void moe_gemm_kernel(const float* __restrict__ x,
                     const float* __restrict__ w_all,
                     const float* __restrict__ bias_all,
                     float* __restrict__ out) {
    const int b = blockIdx.z;
    const int e = g_expert_idx[b];

    const float* __restrict__ A    = x       + (size_t)b * NS  * NIN;   // [S, IN]
    const float* __restrict__ Wm   = w_all   + (size_t)e * NOUT * NIN;  // [OUT, IN]
    const float* __restrict__ bias = bias_all + (size_t)e * NOUT;       // [OUT]
    float* __restrict__ C          = out     + (size_t)b * NS * NOUT;   // [S, OUT]

    __shared__ float As[BK][BM];   // transposed: As[k][m]
    __shared__ float Bs[BK][BN];   // transposed: Bs[k][n]

    const int tid = threadIdx.x;
    const int ty  = tid >> 4;      // 0..15  (M direction)
    const int tx  = tid & 15;      // 0..15  (N direction)

    const int block_row = blockIdx.y * BM;   // S offset
    const int block_col = blockIdx.x * BN;   // OUT offset

    // Global load mapping: tile is 128 rows x 16 floats = 512 float4.
    // 256 threads -> 2 float4 each (rows r and r+64).
    const int ld_row  = tid >> 2;          // 0..63
    const int ld_col4 = (tid & 3) << 2;    // {0,4,8,12}

    float acc[TM][TN];
#pragma unroll
    for (int i = 0; i < TM; i++)
#pragma unroll
        for (int j = 0; j < TN; j++)
            acc[i][j] = 0.0f;

    for (int k0 = 0; k0 < NIN; k0 += BK) {
        // Load A tile (transpose into As[k][m])
#pragma unroll
        for (int i = 0; i < 2; i++) {
            int row = ld_row + i * 64;
            float4 v = *(const float4*)(A + (size_t)(block_row + row) * NIN + k0 + ld_col4);
            As[ld_col4 + 0][row] = v.x;
            As[ld_col4 + 1][row] = v.y;
            As[ld_col4 + 2][row] = v.z;
            As[ld_col4 + 3][row] = v.w;
        }
        // Load W tile (transpose into Bs[k][n])
#pragma unroll
        for (int i = 0; i < 2; i++) {
            int row = ld_row + i * 64;
            float4 v = *(const float4*)(Wm + (size_t)(block_col + row) * NIN + k0 + ld_col4);
            Bs[ld_col4 + 0][row] = v.x;
            Bs[ld_col4 + 1][row] = v.y;
            Bs[ld_col4 + 2][row] = v.z;
            Bs[ld_col4 + 3][row] = v.w;
        }
        __syncthreads();

#pragma unroll
        for (int k = 0; k < BK; k++) {
            float4 a0 = *(const float4*)&As[k][ty * TM];
            float4 a1 = *(const float4*)&As[k][ty * TM + 4];
            float4 b0 = *(const float4*)&Bs[k][tx * TN];
            float4 b1 = *(const float4*)&Bs[k][tx * TN + 4];
            float af[TM] = {a0.x, a0.y, a0.z, a0.w, a1.x, a1.y, a1.z, a1.w};
            float bf[TN] = {b0.x, b0.y, b0.z, b0.w, b1.x, b1.y, b1.z, b1.w};
#pragma unroll
            for (int i = 0; i < TM; i++)
#pragma unroll
                for (int j = 0; j < TN; j++)
                    acc[i][j] = fmaf(af[i], bf[j], acc[i][j]);
        }
        __syncthreads();
    }

    // Epilogue: add bias, vectorized stores (rows are contiguous in OUT dim)
    float bf0[TN];
#pragma unroll
    for (int j = 0; j < TN; j++)
        bf0[j] = bias[block_col + tx * TN + j];

#pragma unroll
    for (int i = 0; i < TM; i++) {
        int m = block_row + ty * TM + i;
        float* crow = C + (size_t)m * NOUT + block_col + tx * TN;
        float4 v0, v1;
        v0.x = acc[i][0] + bf0[0];
        v0.y = acc[i][1] + bf0[1];
        v0.z = acc[i][2] + bf0[2];
        v0.w = acc[i][3] + bf0[3];
        v1.x = acc[i][4] + bf0[4];
        v1.y = acc[i][5] + bf0[5];
        v1.z = acc[i][6] + bf0[6];
        v1.w = acc[i][7] + bf0[7];
        *(float4*)(crow + 0) = v0;
        *(float4*)(crow + 4) = v1;
    }
}

// ---------------------------------------------------------------------------
// kernel_launch
// Inputs (metadata order): x [B,S,IN] f32, expert_probs [B,E] f32,
//                          expert_weights [E,OUT,IN] f32, expert_biases [E,OUT] f32
// Output: x_out [B,S,OUT] f32, optionally followed by expert_idx [B] (as f32).
// ---------------------------------------------------------------------------
extern "C" void kernel_launch(void* const* d_in, const int* in_sizes, int n_in,
                              void* d_out, int out_size) {
    const float* x     = (const float*)d_in[0];
    const float* probs = (const float*)d_in[1];
    const float* w     = (const float*)d_in[2];
    const float* bias  = (const float*)d_in[3];
    float* out = (float*)d_out;

    const long long main_elems = (long long)NB * NS * NOUT;  // 134,217,728
    long long tail_ll = (long long)out_size - main_elems;
    int n_tail = 0;
    float* out_tail = nullptr;
    if (tail_ll > 0) {
        n_tail = (int)(tail_ll < NB ? tail_ll : NB);
        out_tail = out + main_elems;
    }

    route_kernel<<<1, 32>>>(probs, out_tail, n_tail);

    dim3 grid(NOUT / BN, NS / BM, NB);  // (32, 16, 16) = 8192 CTAs
    moe_gemm_kernel<<<grid, 256>>>(x, w, bias, out);
}

// round 6
// speedup vs baseline: 2.1270x; 2.1270x over previous
#include <cuda_runtime.h>
#include <cuda_bf16.h>
#include <cstdint>

// Problem constants: E=8, OUT=4096, IN=1024, B=16, S=2048
#define NB   16
#define NS   2048
#define NIN  1024
#define NOUT 4096
#define NE   8

// ---------------------------------------------------------------------------
// Device scratch (no allocations allowed): routing + bf16 hi/lo splits.
// ---------------------------------------------------------------------------
__device__ int g_expert_idx[NB];
__device__ __nv_bfloat16 g_x_hi[(size_t)NB * NS * NIN];
__device__ __nv_bfloat16 g_x_lo[(size_t)NB * NS * NIN];
__device__ __nv_bfloat16 g_w_hi[(size_t)NE * NOUT * NIN];
__device__ __nv_bfloat16 g_w_lo[(size_t)NE * NOUT * NIN];

// ---------------------------------------------------------------------------
// PTX helpers (target-neutral: cp.async / ldmatrix / mma.sync)
// ---------------------------------------------------------------------------
__device__ __forceinline__ uint32_t smem_u32(const void* p) {
    uint32_t a;
    asm("{ .reg .u64 t; cvta.to.shared.u64 t, %1; cvt.u32.u64 %0, t; }"
        : "=r"(a) : "l"(p));
    return a;
}

__device__ __forceinline__ void cp16(uint32_t dst, const void* src) {
    asm volatile("cp.async.cg.shared.global [%0], [%1], 16;" :: "r"(dst), "l"(src));
}
#define CP_COMMIT()   asm volatile("cp.async.commit_group;" ::: "memory")
#define CP_WAIT_2()   asm volatile("cp.async.wait_group 2;" ::: "memory")

__device__ __forceinline__ void ldsm_x4(uint32_t* r, uint32_t a) {
    asm volatile("ldmatrix.sync.aligned.m8n8.x4.shared.b16 {%0,%1,%2,%3}, [%4];"
                 : "=r"(r[0]), "=r"(r[1]), "=r"(r[2]), "=r"(r[3]) : "r"(a));
}
__device__ __forceinline__ void ldsm_x2(uint32_t* r, uint32_t a) {
    asm volatile("ldmatrix.sync.aligned.m8n8.x2.shared.b16 {%0,%1}, [%2];"
                 : "=r"(r[0]), "=r"(r[1]) : "r"(a));
}

__device__ __forceinline__ void mma_bf16(float* d, const uint32_t* a, const uint32_t* b) {
    asm volatile(
        "mma.sync.aligned.m16n8k16.row.col.f32.bf16.bf16.f32 "
        "{%0,%1,%2,%3}, {%4,%5,%6,%7}, {%8,%9}, {%0,%1,%2,%3};"
        : "+f"(d[0]), "+f"(d[1]), "+f"(d[2]), "+f"(d[3])
        : "r"(a[0]), "r"(a[1]), "r"(a[2]), "r"(a[3]), "r"(b[0]), "r"(b[1]));
}

// ---------------------------------------------------------------------------
// Kernel: top-1 routing (+ optional idx tail in output)
// ---------------------------------------------------------------------------
__global__ void route_kernel(const float* __restrict__ probs,
                             float* __restrict__ out_tail, int n_tail) {
    int b = threadIdx.x;
    if (b < NB) {
        const float* p = probs + b * NE;
        float best = p[0];
        int bi = 0;
#pragma unroll
        for (int e = 1; e < NE; e++) {
            float v = p[e];
            if (v > best) { best = v; bi = e; }
        }
        g_expert_idx[b] = bi;
        if (out_tail != nullptr && b < n_tail) out_tail[b] = (float)bi;
    }
}

// ---------------------------------------------------------------------------
// Kernel: fp32 -> (bf16 hi, bf16 lo) split.  which=0 -> x buffers, 1 -> w.
// ---------------------------------------------------------------------------
__global__ void split_kernel(const float4* __restrict__ src, int n4, int which) {
    int i = blockIdx.x * blockDim.x + threadIdx.x;
    if (i >= n4) return;
    __nv_bfloat162* hi2 = (__nv_bfloat162*)(which ? g_w_hi : g_x_hi);
    __nv_bfloat162* lo2 = (__nv_bfloat162*)(which ? g_w_lo : g_x_lo);
    float4 v = src[i];
    __nv_bfloat16 hx = __float2bfloat16(v.x);
    __nv_bfloat16 hy = __float2bfloat16(v.y);
    __nv_bfloat16 hz = __float2bfloat16(v.z);
    __nv_bfloat16 hw = __float2bfloat16(v.w);
    __nv_bfloat16 lx = __float2bfloat16(v.x - __bfloat162float(hx));
    __nv_bfloat16 ly = __float2bfloat16(v.y - __bfloat162float(hy));
    __nv_bfloat16 lz = __float2bfloat16(v.z - __bfloat162float(hz));
    __nv_bfloat16 lw = __float2bfloat16(v.w - __bfloat162float(hw));
    hi2[2 * i + 0] = __nv_bfloat162{hx, hy};
    hi2[2 * i + 1] = __nv_bfloat162{hz, hw};
    lo2[2 * i + 0] = __nv_bfloat162{lx, ly};
    lo2[2 * i + 1] = __nv_bfloat162{lz, lw};
}

// ---------------------------------------------------------------------------
// bf16x3 GEMM via mma.sync.m16n8k16 (HMMA), 128x128 tile, BK=32, 4 stages.
//   C[b][m][n] = sum_k x[b][m][k] * W[e(b)][n][k] + bias[e(b)][n]
// ---------------------------------------------------------------------------
#define BM 128
#define BN 128
#define BK 32
#define STAGES 4
#define ROWB 80                     // padded row stride in bytes (32 bf16 + 8 pad)
#define ARR_BYTES (128 * ROWB)      // 10240 per operand array
#define A_HI 0
#define A_LO (1 * ARR_BYTES)
#define B_HI (2 * ARR_BYTES)
#define B_LO (3 * ARR_BYTES)
#define STAGE_BYTES (4 * ARR_BYTES) // 40960
#define KBLOCKS (NIN / BK)          // 32

__global__ __launch_bounds__(256, 1)
void moe_mma_gemm(const float* __restrict__ bias_all, float* __restrict__ out) {
    extern __shared__ char dyn_smem[];
    const uint32_t sbase = smem_u32(dyn_smem);

    const int tid = threadIdx.x;
    const int wid = tid >> 5;
    const int l   = tid & 31;
    const int warp_m = wid & 3;     // 4 M-groups of 32 rows
    const int warp_n = wid >> 2;    // 2 N-groups of 64 cols

    const int b = blockIdx.z;
    const int e = g_expert_idx[b];
    const int block_row = blockIdx.y * BM;
    const int block_col = blockIdx.x * BN;

    const __nv_bfloat16* xa_hi = g_x_hi + (size_t)b * NS * NIN;
    const __nv_bfloat16* xa_lo = g_x_lo + (size_t)b * NS * NIN;
    const __nv_bfloat16* wb_hi = g_w_hi + (size_t)e * NOUT * NIN;
    const __nv_bfloat16* wb_lo = g_w_lo + (size_t)e * NOUT * NIN;

    // cp.async task mapping: 512 chunks of 16B per array; 2 per thread.
    const int c0r = (tid * 2) >> 2;        // row of first chunk
    const int c0c = (tid * 2) & 3;         // col16 of first chunk (0..3)

    auto load_stage = [&](int stage, int k0) {
        uint32_t sb = sbase + stage * STAGE_BYTES;
#pragma unroll
        for (int u = 0; u < 2; u++) {
            int r = c0r;           // two chunks are same row, cols c0c, c0c+1
            int cc = c0c + u;
            uint32_t so = (uint32_t)r * ROWB + cc * 16;
            size_t ga = (size_t)(block_row + r) * NIN + k0 + cc * 8;
            size_t gb = (size_t)(block_col + r) * NIN + k0 + cc * 8;
            cp16(sb + A_HI + so, xa_hi + ga);
            cp16(sb + A_LO + so, xa_lo + ga);
            cp16(sb + B_HI + so, wb_hi + gb);
            cp16(sb + B_LO + so, wb_lo + gb);
        }
        CP_COMMIT();
    };

    // Accumulators: 2 m-tiles x 8 n-tiles x 4 floats
    float acc[2][8][4];
#pragma unroll
    for (int i = 0; i < 2; i++)
#pragma unroll
        for (int j = 0; j < 8; j++)
#pragma unroll
            for (int q = 0; q < 4; q++) acc[i][j][q] = 0.0f;

    // ldmatrix lane address components
    const uint32_t a_row = (uint32_t)(warp_m * 32 + (l & 15));
    const uint32_t a_kb  = (uint32_t)((l >> 4) & 1) * 16;       // byte offset within k16
    const uint32_t b_row = (uint32_t)(warp_n * 64 + (l & 7));
    const uint32_t b_kb  = (uint32_t)((l >> 3) & 1) * 16;

    // Prologue: 3 stages in flight
    load_stage(0, 0);
    load_stage(1, BK);
    load_stage(2, 2 * BK);

    for (int kb = 0; kb < KBLOCKS; kb++) {
        CP_WAIT_2();            // exactly stage kb's group retired
        __syncthreads();        // all warps done with the buffer we refill below

        if (kb + 3 < KBLOCKS) load_stage((kb + 3) & (STAGES - 1), (kb + 3) * BK);
        CP_COMMIT();            // keep group count uniform (empty when no loads)

        const uint32_t sb = sbase + (kb & (STAGES - 1)) * STAGE_BYTES;
#pragma unroll
        for (int ks = 0; ks < 2; ks++) {
            const uint32_t kso = ks * 32;  // k-step byte offset (16 bf16)
            uint32_t a_hi[2][4], a_lo[2][4], b_hi[8][2], b_lo[8][2];

            // A_hi fragments
#pragma unroll
            for (int mt = 0; mt < 2; mt++)
                ldsm_x4(a_hi[mt], sb + A_HI + (a_row + mt * 16) * ROWB + kso + a_kb);
            // B_hi fragments
#pragma unroll
            for (int nt = 0; nt < 8; nt++)
                ldsm_x2(b_hi[nt], sb + B_HI + (b_row + nt * 8) * ROWB + kso + b_kb);
            // pass 1: hi*hi
#pragma unroll
            for (int mt = 0; mt < 2; mt++)
#pragma unroll
                for (int nt = 0; nt < 8; nt++)
                    mma_bf16(acc[mt][nt], a_hi[mt], b_hi[nt]);

            // B_lo, pass 2: hi*lo
#pragma unroll
            for (int nt = 0; nt < 8; nt++)
                ldsm_x2(b_lo[nt], sb + B_LO + (b_row + nt * 8) * ROWB + kso + b_kb);
#pragma unroll
            for (int mt = 0; mt < 2; mt++)
#pragma unroll
                for (int nt = 0; nt < 8; nt++)
                    mma_bf16(acc[mt][nt], a_hi[mt], b_lo[nt]);

            // A_lo, pass 3: lo*hi
#pragma unroll
            for (int mt = 0; mt < 2; mt++)
                ldsm_x4(a_lo[mt], sb + A_LO + (a_row + mt * 16) * ROWB + kso + a_kb);
#pragma unroll
            for (int mt = 0; mt < 2; mt++)
#pragma unroll
                for (int nt = 0; nt < 8; nt++)
                    mma_bf16(acc[mt][nt], a_lo[mt], b_hi[nt]);
        }
    }

    // ---- epilogue: bias + direct stores ----
    const float* bias = bias_all + (size_t)e * NOUT;
    const int m0 = block_row + warp_m * 32 + (l >> 2);
    const int n0 = block_col + warp_n * 64 + (l & 3) * 2;
    float* outb = out + (size_t)b * NS * NOUT;

#pragma unroll
    for (int nt = 0; nt < 8; nt++) {
        int n = n0 + nt * 8;
        float2 bb = *(const float2*)(bias + n);
#pragma unroll
        for (int mt = 0; mt < 2; mt++) {
            int r0 = m0 + mt * 16;
            float2 v0 = { acc[mt][nt][0] + bb.x, acc[mt][nt][1] + bb.y };
            float2 v1 = { acc[mt][nt][2] + bb.x, acc[mt][nt][3] + bb.y };
            *(float2*)(outb + (size_t)r0 * NOUT + n)       = v0;
            *(float2*)(outb + (size_t)(r0 + 8) * NOUT + n) = v1;
        }
    }
}

// ---------------------------------------------------------------------------
// kernel_launch
// Inputs: x [B,S,IN] f32, expert_probs [B,E] f32,
//         expert_weights [E,OUT,IN] f32, expert_biases [E,OUT] f32
// ---------------------------------------------------------------------------
extern "C" void kernel_launch(void* const* d_in, const int* in_sizes, int n_in,
                              void* d_out, int out_size) {
    const float* x     = (const float*)d_in[0];
    const float* probs = (const float*)d_in[1];
    const float* w     = (const float*)d_in[2];
    const float* bias  = (const float*)d_in[3];
    float* out = (float*)d_out;

    const long long main_elems = (long long)NB * NS * NOUT;
    long long tail_ll = (long long)out_size - main_elems;
    int n_tail = 0;
    float* out_tail = nullptr;
    if (tail_ll > 0) {
        n_tail = (int)(tail_ll < NB ? tail_ll : NB);
        out_tail = out + main_elems;
    }

    const int n4_x = (NB * NS * NIN) / 4;
    const int n4_w = (NE * NOUT * NIN) / 4;
    split_kernel<<<(n4_x + 255) / 256, 256>>>((const float4*)x, n4_x, 0);
    split_kernel<<<(n4_w + 255) / 256, 256>>>((const float4*)w, n4_w, 1);

    route_kernel<<<1, 32>>>(probs, out_tail, n_tail);

    const int dyn_smem = STAGES * STAGE_BYTES;   // 163,840 bytes
    cudaFuncSetAttribute(moe_mma_gemm, cudaFuncAttributeMaxDynamicSharedMemorySize, dyn_smem);
    dim3 grid(NOUT / BN, NS / BM, NB);           // (32, 16, 16) = 8192 CTAs
    moe_mma_gemm<<<grid, 256, dyn_smem>>>(bias, out);
}

// round 7
// speedup vs baseline: 3.5721x; 1.6794x over previous
#include <cuda_runtime.h>
#include <cuda_bf16.h>
#include <cstdint>

// Problem constants: E=8, OUT=4096, IN=1024, B=16, S=2048
#define NB   16
#define NS   2048
#define NIN  1024
#define NOUT 4096
#define NE   8

__device__ int g_expert_idx[NB];

// ---------------------------------------------------------------------------
// PTX helpers (target-neutral: cp.async / ldmatrix / mma.sync tf32)
// ---------------------------------------------------------------------------
__device__ __forceinline__ uint32_t smem_u32(const void* p) {
    uint32_t a;
    asm("{ .reg .u64 t; cvta.to.shared.u64 t, %1; cvt.u32.u64 %0, t; }"
        : "=r"(a) : "l"(p));
    return a;
}

__device__ __forceinline__ void cp16(uint32_t dst, const void* src) {
    asm volatile("cp.async.cg.shared.global [%0], [%1], 16;" :: "r"(dst), "l"(src));
}
#define CP_COMMIT()   asm volatile("cp.async.commit_group;" ::: "memory")
#define CP_WAIT_1()   asm volatile("cp.async.wait_group 1;" ::: "memory")

__device__ __forceinline__ void ldsm_x4(uint32_t* r, uint32_t a) {
    asm volatile("ldmatrix.sync.aligned.m8n8.x4.shared.b16 {%0,%1,%2,%3}, [%4];"
                 : "=r"(r[0]), "=r"(r[1]), "=r"(r[2]), "=r"(r[3]) : "r"(a));
}

// fp32 (bits) -> tf32 with round-to-nearest (unbiased; truncation would bias)
__device__ __forceinline__ uint32_t f2tf(uint32_t x) {
    uint32_t d;
    asm("cvt.rna.tf32.f32 %0, %1;" : "=r"(d) : "f"(__uint_as_float(x)));
    return d;
}

__device__ __forceinline__ void mma_tf32(float* d, const uint32_t* a, const uint32_t* b) {
    asm volatile(
        "mma.sync.aligned.m16n8k8.row.col.f32.tf32.tf32.f32 "
        "{%0,%1,%2,%3}, {%4,%5,%6,%7}, {%8,%9}, {%0,%1,%2,%3};"
        : "+f"(d[0]), "+f"(d[1]), "+f"(d[2]), "+f"(d[3])
        : "r"(a[0]), "r"(a[1]), "r"(a[2]), "r"(a[3]), "r"(b[0]), "r"(b[1]));
}

// ---------------------------------------------------------------------------
// Kernel: top-1 routing (+ optional idx tail in output)
// ---------------------------------------------------------------------------
__global__ void route_kernel(const float* __restrict__ probs,
                             float* __restrict__ out_tail, int n_tail) {
    int b = threadIdx.x;
    if (b < NB) {
        const float* p = probs + b * NE;
        float best = p[0];
        int bi = 0;
#pragma unroll
        for (int e = 1; e < NE; e++) {
            float v = p[e];
            if (v > best) { best = v; bi = e; }
        }
        g_expert_idx[b] = bi;
        if (out_tail != nullptr && b < n_tail) out_tail[b] = (float)bi;
    }
}

// ---------------------------------------------------------------------------
// Single-pass TF32 GEMM via mma.sync.m16n8k8.
//   Tile: 128(M) x 256(N), BK=32 fp32, 3-stage cp.async, 8 warps (2m x 4n),
//   warp tile 64x64.  C[b][m][n] = x[b][m][:] . W[e(b)][n][:] + bias[e(b)][n]
// ---------------------------------------------------------------------------
#define BM 128
#define BN 256
#define BK 32
#define STAGES 3
#define ROWB 144                    // 128B row (32 fp32) + 16B pad -> conflict-free ldsm
#define A_OFF 0
#define B_OFF (128 * ROWB)          // 18432
#define STAGE_BYTES (B_OFF + 256 * ROWB)   // 55296
#define KBLOCKS (NIN / BK)          // 32

__global__ __launch_bounds__(256, 1)
void moe_tf32_gemm(const float* __restrict__ x,
                   const float* __restrict__ w_all,
                   const float* __restrict__ bias_all,
                   float* __restrict__ out) {
    extern __shared__ char dyn_smem[];
    const uint32_t sbase = smem_u32(dyn_smem);

    const int tid = threadIdx.x;
    const int wid = tid >> 5;
    const int l   = tid & 31;
    const int warp_m = wid >> 2;    // 0..1  (64 rows each)
    const int warp_n = wid & 3;     // 0..3  (64 cols each)

    const int b = blockIdx.z;
    const int e = g_expert_idx[b];
    const int block_row = blockIdx.y * BM;
    const int block_col = blockIdx.x * BN;

    const float* __restrict__ Ag = x     + (size_t)b * NS * NIN;
    const float* __restrict__ Bg = w_all + (size_t)e * NOUT * NIN;

    // cp.async: A = 1024 16B chunks (4/thread), B = 2048 (8/thread)
    auto load_stage = [&](int stage, int k0) {
        uint32_t sb = sbase + stage * STAGE_BYTES;
#pragma unroll
        for (int u = 0; u < 4; u++) {
            int c = tid + u * 256;
            int r = c >> 3, j = c & 7;
            cp16(sb + A_OFF + (uint32_t)r * ROWB + j * 16,
                 Ag + (size_t)(block_row + r) * NIN + k0 + j * 4);
        }
#pragma unroll
        for (int u = 0; u < 8; u++) {
            int c = tid + u * 256;
            int r = c >> 3, j = c & 7;
            cp16(sb + B_OFF + (uint32_t)r * ROWB + j * 16,
                 Bg + (size_t)(block_col + r) * NIN + k0 + j * 4);
        }
        CP_COMMIT();
    };

    // Accumulators: 4 m-tiles(16) x 8 n-tiles(8) x 4 floats = 128 regs
    float acc[4][8][4];
#pragma unroll
    for (int i = 0; i < 4; i++)
#pragma unroll
        for (int j = 0; j < 8; j++)
#pragma unroll
            for (int q = 0; q < 4; q++) acc[i][j][q] = 0.0f;

    // ldmatrix lane-address components (fp32-as-b16 trick):
    // A x4: mats = {rows m..m+7 | k0-3, rows m+8.. | k0-3, rows m.. | k4-7, rows m+8 | k4-7}
    const uint32_t a_lrow = (uint32_t)(l & 15);
    const uint32_t a_lb   = (uint32_t)((l >> 4) & 1) * 16;
    // B x4 covers two n-tiles: {n..n+7|k0-3, n..n+7|k4-7, n+8..|k0-3, n+8..|k4-7}
    const uint32_t b_lrow = (uint32_t)((l & 7) + (((l >> 4) & 1) << 3));
    const uint32_t b_lb   = (uint32_t)((l >> 3) & 1) * 16;

    // Prologue: stages 0,1 in flight
    load_stage(0, 0);
    load_stage(1, BK);

    for (int kb = 0; kb < KBLOCKS; kb++) {
        CP_WAIT_1();            // own groups: stage kb complete
        __syncthreads();        // everyone's loads visible; buffer (kb+2)%3 free

        if (kb + 2 < KBLOCKS) load_stage((kb + 2) % STAGES, (kb + 2) * BK);
        else CP_COMMIT();       // keep group count uniform

        const uint32_t sb = sbase + (kb % STAGES) * STAGE_BYTES;
        const uint32_t a_base = sb + A_OFF + (warp_m * 64 + a_lrow) * ROWB + a_lb;
        const uint32_t b_base = sb + B_OFF + (warp_n * 64 + b_lrow) * ROWB + b_lb;

#pragma unroll
        for (int ks = 0; ks < 4; ks++) {        // 4 x k=8
            const uint32_t kso = ks * 32;
            uint32_t af[4][4], bf[8][2];
#pragma unroll
            for (int mt = 0; mt < 4; mt++)
                ldsm_x4(af[mt], a_base + mt * (16 * ROWB) + kso);
#pragma unroll
            for (int np = 0; np < 4; np++) {
                uint32_t t[4];
                ldsm_x4(t, b_base + np * (16 * ROWB) + kso);
                bf[2 * np + 0][0] = t[0]; bf[2 * np + 0][1] = t[1];
                bf[2 * np + 1][0] = t[2]; bf[2 * np + 1][1] = t[3];
            }
            // RNA tf32 rounding in-register
#pragma unroll
            for (int mt = 0; mt < 4; mt++)
#pragma unroll
                for (int q = 0; q < 4; q++) af[mt][q] = f2tf(af[mt][q]);
#pragma unroll
            for (int nt = 0; nt < 8; nt++) {
                bf[nt][0] = f2tf(bf[nt][0]);
                bf[nt][1] = f2tf(bf[nt][1]);
            }
#pragma unroll
            for (int mt = 0; mt < 4; mt++)
#pragma unroll
                for (int nt = 0; nt < 8; nt++)
                    mma_tf32(acc[mt][nt], af[mt], bf[nt]);
        }
    }

    // ---- epilogue: bias + direct stores ----
    const float* bias = bias_all + (size_t)e * NOUT;
    float* outb = out + (size_t)b * NS * NOUT;
    const int r0 = block_row + warp_m * 64 + (l >> 2);
    const int c0 = block_col + warp_n * 64 + (l & 3) * 2;

#pragma unroll
    for (int nt = 0; nt < 8; nt++) {
        int cc = c0 + nt * 8;
        float2 bb = *(const float2*)(bias + cc);
#pragma unroll
        for (int mt = 0; mt < 4; mt++) {
            int rr = r0 + mt * 16;
            float2 v0 = { acc[mt][nt][0] + bb.x, acc[mt][nt][1] + bb.y };
            float2 v1 = { acc[mt][nt][2] + bb.x, acc[mt][nt][3] + bb.y };
            *(float2*)(outb + (size_t)rr * NOUT + cc)       = v0;
            *(float2*)(outb + (size_t)(rr + 8) * NOUT + cc) = v1;
        }
    }
}

// ---------------------------------------------------------------------------
// kernel_launch
// Inputs: x [B,S,IN] f32, expert_probs [B,E] f32,
//         expert_weights [E,OUT,IN] f32, expert_biases [E,OUT] f32
// ---------------------------------------------------------------------------
extern "C" void kernel_launch(void* const* d_in, const int* in_sizes, int n_in,
                              void* d_out, int out_size) {
    const float* x     = (const float*)d_in[0];
    const float* probs = (const float*)d_in[1];
    const float* w     = (const float*)d_in[2];
    const float* bias  = (const float*)d_in[3];
    float* out = (float*)d_out;

    const long long main_elems = (long long)NB * NS * NOUT;
    long long tail_ll = (long long)out_size - main_elems;
    int n_tail = 0;
    float* out_tail = nullptr;
    if (tail_ll > 0) {
        n_tail = (int)(tail_ll < NB ? tail_ll : NB);
        out_tail = out + main_elems;
    }

    route_kernel<<<1, 32>>>(probs, out_tail, n_tail);

    const int dyn_smem = STAGES * STAGE_BYTES;   // 165,888 bytes
    cudaFuncSetAttribute(moe_tf32_gemm, cudaFuncAttributeMaxDynamicSharedMemorySize, dyn_smem);
    dim3 grid(NOUT / BN, NS / BM, NB);           // (16, 16, 16) = 4096 CTAs
    moe_tf32_gemm<<<grid, 256, dyn_smem>>>(x, w, bias, out);
}

// round 8
// speedup vs baseline: 3.6216x; 1.0139x over previous
#include <cuda_runtime.h>
#include <cuda_bf16.h>
#include <cstdint>

// Problem constants: E=8, OUT=4096, IN=1024, B=16, S=2048
#define NB   16
#define NS   2048
#define NIN  1024
#define NOUT 4096
#define NE   8

// Device scratch (no allocations allowed): routing + tf32-rounded copies.
__device__ int g_expert_idx[NB];
__device__ float g_x_tf[(size_t)NB * NS * NIN];     // 128 MB
__device__ float g_w_tf[(size_t)NE * NOUT * NIN];   // 128 MB

// ---------------------------------------------------------------------------
// PTX helpers (target-neutral: cp.async / ldmatrix / mma.sync tf32)
// ---------------------------------------------------------------------------
__device__ __forceinline__ uint32_t smem_u32(const void* p) {
    uint32_t a;
    asm("{ .reg .u64 t; cvta.to.shared.u64 t, %1; cvt.u32.u64 %0, t; }"
        : "=r"(a) : "l"(p));
    return a;
}

__device__ __forceinline__ void cp16(uint32_t dst, const void* src) {
    asm volatile("cp.async.cg.shared.global [%0], [%1], 16;" :: "r"(dst), "l"(src));
}
#define CP_COMMIT()   asm volatile("cp.async.commit_group;" ::: "memory")
#define CP_WAIT_1()   asm volatile("cp.async.wait_group 1;" ::: "memory")

__device__ __forceinline__ void ldsm_x4(uint32_t* r, uint32_t a) {
    asm volatile("ldmatrix.sync.aligned.m8n8.x4.shared.b16 {%0,%1,%2,%3}, [%4];"
                 : "=r"(r[0]), "=r"(r[1]), "=r"(r[2]), "=r"(r[3]) : "r"(a));
}

// fp32 -> tf32 canonical bits, round-to-nearest (unbiased)
__device__ __forceinline__ uint32_t f2tf(float x) {
    uint32_t d;
    asm("cvt.rna.tf32.f32 %0, %1;" : "=r"(d) : "f"(x));
    return d;
}

__device__ __forceinline__ void mma_tf32(float* d, const uint32_t* a, const uint32_t* b) {
    asm volatile(
        "mma.sync.aligned.m16n8k8.row.col.f32.tf32.tf32.f32 "
        "{%0,%1,%2,%3}, {%4,%5,%6,%7}, {%8,%9}, {%0,%1,%2,%3};"
        : "+f"(d[0]), "+f"(d[1]), "+f"(d[2]), "+f"(d[3])
        : "r"(a[0]), "r"(a[1]), "r"(a[2]), "r"(a[3]), "r"(b[0]), "r"(b[1]));
}

// ---------------------------------------------------------------------------
// Kernel: top-1 routing (+ optional idx tail in output)
// ---------------------------------------------------------------------------
__global__ void route_kernel(const float* __restrict__ probs,
                             float* __restrict__ out_tail, int n_tail) {
    int b = threadIdx.x;
    if (b < NB) {
        const float* p = probs + b * NE;
        float best = p[0];
        int bi = 0;
#pragma unroll
        for (int e = 1; e < NE; e++) {
            float v = p[e];
            if (v > best) { best = v; bi = e; }
        }
        g_expert_idx[b] = bi;
        if (out_tail != nullptr && b < n_tail) out_tail[b] = (float)bi;
    }
}

// ---------------------------------------------------------------------------
// Kernel: fp32 -> tf32-canonical fp32 bits (pre-rounding pass).
// which=0 -> g_x_tf, 1 -> g_w_tf.
// ---------------------------------------------------------------------------
__global__ void tf32_round_kernel(const float4* __restrict__ src, int n4, int which) {
    int i = blockIdx.x * blockDim.x + threadIdx.x;
    if (i >= n4) return;
    uint4* dst = (uint4*)(which ? g_w_tf : g_x_tf);
    float4 v = src[i];
    uint4 o;
    o.x = f2tf(v.x);
    o.y = f2tf(v.y);
    o.z = f2tf(v.z);
    o.w = f2tf(v.w);
    dst[i] = o;
}

// ---------------------------------------------------------------------------
// Single-pass TF32 GEMM via mma.sync.m16n8k8 on pre-rounded operands.
//   Tile: 128(M) x 256(N), BK=32 fp32, 3-stage cp.async, 8 warps (2m x 4n),
//   warp tile 64x64.  C[b][m][n] = x[b][m][:] . W[e(b)][n][:] + bias[e(b)][n]
// ---------------------------------------------------------------------------
#define BM 128
#define BN 256
#define BK 32
#define STAGES 3
#define ROWB 144                    // 128B row (32 fp32) + 16B pad -> conflict-free ldsm
#define A_OFF 0
#define B_OFF (128 * ROWB)          // 18432
#define STAGE_BYTES (B_OFF + 256 * ROWB)   // 55296
#define KBLOCKS (NIN / BK)          // 32

__global__ __launch_bounds__(256, 1)
void moe_tf32_gemm(const float* __restrict__ bias_all,
                   float* __restrict__ out) {
    extern __shared__ char dyn_smem[];
    const uint32_t sbase = smem_u32(dyn_smem);

    const int tid = threadIdx.x;
    const int wid = tid >> 5;
    const int l   = tid & 31;
    const int warp_m = wid >> 2;    // 0..1  (64 rows each)
    const int warp_n = wid & 3;     // 0..3  (64 cols each)

    const int b = blockIdx.z;
    const int e = g_expert_idx[b];
    const int block_row = blockIdx.y * BM;
    const int block_col = blockIdx.x * BN;

    const float* __restrict__ Ag = g_x_tf + (size_t)b * NS * NIN;
    const float* __restrict__ Bg = g_w_tf + (size_t)e * NOUT * NIN;

    // cp.async: A = 1024 16B chunks (4/thread), B = 2048 (8/thread)
    auto load_stage = [&](int stage, int k0) {
        uint32_t sb = sbase + stage * STAGE_BYTES;
#pragma unroll
        for (int u = 0; u < 4; u++) {
            int c = tid + u * 256;
            int r = c >> 3, j = c & 7;
            cp16(sb + A_OFF + (uint32_t)r * ROWB + j * 16,
                 Ag + (size_t)(block_row + r) * NIN + k0 + j * 4);
        }
#pragma unroll
        for (int u = 0; u < 8; u++) {
            int c = tid + u * 256;
            int r = c >> 3, j = c & 7;
            cp16(sb + B_OFF + (uint32_t)r * ROWB + j * 16,
                 Bg + (size_t)(block_col + r) * NIN + k0 + j * 4);
        }
        CP_COMMIT();
    };

    // Accumulators: 4 m-tiles(16) x 8 n-tiles(8) x 4 floats = 128 regs
    float acc[4][8][4];
#pragma unroll
    for (int i = 0; i < 4; i++)
#pragma unroll
        for (int j = 0; j < 8; j++)
#pragma unroll
            for (int q = 0; q < 4; q++) acc[i][j][q] = 0.0f;

    // ldmatrix lane-address components (fp32-as-b16 trick):
    const uint32_t a_lrow = (uint32_t)(l & 15);
    const uint32_t a_lb   = (uint32_t)((l >> 4) & 1) * 16;
    const uint32_t b_lrow = (uint32_t)((l & 7) + (((l >> 4) & 1) << 3));
    const uint32_t b_lb   = (uint32_t)((l >> 3) & 1) * 16;

    // Prologue: stages 0,1 in flight
    load_stage(0, 0);
    load_stage(1, BK);

    for (int kb = 0; kb < KBLOCKS; kb++) {
        CP_WAIT_1();            // stage kb complete
        __syncthreads();        // loads visible; buffer (kb+2)%3 free

        if (kb + 2 < KBLOCKS) load_stage((kb + 2) % STAGES, (kb + 2) * BK);
        else CP_COMMIT();       // keep group count uniform

        const uint32_t sb = sbase + (kb % STAGES) * STAGE_BYTES;
        const uint32_t a_base = sb + A_OFF + (warp_m * 64 + a_lrow) * ROWB + a_lb;
        const uint32_t b_base = sb + B_OFF + (warp_n * 64 + b_lrow) * ROWB + b_lb;

#pragma unroll
        for (int ks = 0; ks < 4; ks++) {        // 4 x k=8
            const uint32_t kso = ks * 32;
            uint32_t af[4][4], bf[8][2];
#pragma unroll
            for (int mt = 0; mt < 4; mt++)
                ldsm_x4(af[mt], a_base + mt * (16 * ROWB) + kso);
#pragma unroll
            for (int np = 0; np < 4; np++) {
                uint32_t t[4];
                ldsm_x4(t, b_base + np * (16 * ROWB) + kso);
                bf[2 * np + 0][0] = t[0]; bf[2 * np + 0][1] = t[1];
                bf[2 * np + 1][0] = t[2]; bf[2 * np + 1][1] = t[3];
            }
            // Operands are pre-rounded to tf32-canonical bits: no cvt here.
#pragma unroll
            for (int mt = 0; mt < 4; mt++)
#pragma unroll
                for (int nt = 0; nt < 8; nt++)
                    mma_tf32(acc[mt][nt], af[mt], bf[nt]);
        }
    }

    // ---- epilogue: bias + direct stores ----
    const float* bias = bias_all + (size_t)e * NOUT;
    float* outb = out + (size_t)b * NS * NOUT;
    const int r0 = block_row + warp_m * 64 + (l >> 2);
    const int c0 = block_col + warp_n * 64 + (l & 3) * 2;

#pragma unroll
    for (int nt = 0; nt < 8; nt++) {
        int cc = c0 + nt * 8;
        float2 bb = *(const float2*)(bias + cc);
#pragma unroll
        for (int mt = 0; mt < 4; mt++) {
            int rr = r0 + mt * 16;
            float2 v0 = { acc[mt][nt][0] + bb.x, acc[mt][nt][1] + bb.y };
            float2 v1 = { acc[mt][nt][2] + bb.x, acc[mt][nt][3] + bb.y };
            *(float2*)(outb + (size_t)rr * NOUT + cc)       = v0;
            *(float2*)(outb + (size_t)(rr + 8) * NOUT + cc) = v1;
        }
    }
}

// ---------------------------------------------------------------------------
// kernel_launch
// Inputs: x [B,S,IN] f32, expert_probs [B,E] f32,
//         expert_weights [E,OUT,IN] f32, expert_biases [E,OUT] f32
// ---------------------------------------------------------------------------
extern "C" void kernel_launch(void* const* d_in, const int* in_sizes, int n_in,
                              void* d_out, int out_size) {
    const float* x     = (const float*)d_in[0];
    const float* probs = (const float*)d_in[1];
    const float* w     = (const float*)d_in[2];
    const float* bias  = (const float*)d_in[3];
    float* out = (float*)d_out;

    const long long main_elems = (long long)NB * NS * NOUT;
    long long tail_ll = (long long)out_size - main_elems;
    int n_tail = 0;
    float* out_tail = nullptr;
    if (tail_ll > 0) {
        n_tail = (int)(tail_ll < NB ? tail_ll : NB);
        out_tail = out + main_elems;
    }

    // Pre-round x and W to tf32-canonical bits (memory-bound, ~70 us)
    const int n4_x = (NB * NS * NIN) / 4;
    const int n4_w = (NE * NOUT * NIN) / 4;
    tf32_round_kernel<<<(n4_x + 255) / 256, 256>>>((const float4*)x, n4_x, 0);
    tf32_round_kernel<<<(n4_w + 255) / 256, 256>>>((const float4*)w, n4_w, 1);

    route_kernel<<<1, 32>>>(probs, out_tail, n_tail);

    const int dyn_smem = STAGES * STAGE_BYTES;   // 165,888 bytes
    cudaFuncSetAttribute(moe_tf32_gemm, cudaFuncAttributeMaxDynamicSharedMemorySize, dyn_smem);
    dim3 grid(NOUT / BN, NS / BM, NB);           // (16, 16, 16) = 4096 CTAs
    moe_tf32_gemm<<<grid, 256, dyn_smem>>>(bias, out);
}

// round 9
// speedup vs baseline: 3.9549x; 1.0920x over previous
#include <cuda_runtime.h>
#include <cuda_bf16.h>
#include <cstdint>

// Problem constants: E=8, OUT=4096, IN=1024, B=16, S=2048
#define NB   16
#define NS   2048
#define NIN  1024
#define NOUT 4096
#define NE   8

// Device scratch (no allocations allowed): routing + tf32-rounded copies.
__device__ int g_expert_idx[NB];
__device__ float g_x_tf[(size_t)NB * NS * NIN];     // 128 MB
__device__ float g_w_tf[(size_t)NE * NOUT * NIN];   // 128 MB

// ---------------------------------------------------------------------------
// PTX helpers (target-neutral: cp.async / ldmatrix / mma.sync tf32)
// ---------------------------------------------------------------------------
__device__ __forceinline__ uint32_t smem_u32(const void* p) {
    uint32_t a;
    asm("{ .reg .u64 t; cvta.to.shared.u64 t, %1; cvt.u32.u64 %0, t; }"
        : "=r"(a) : "l"(p));
    return a;
}

__device__ __forceinline__ void cp16(uint32_t dst, const void* src) {
    asm volatile("cp.async.cg.shared.global [%0], [%1], 16;" :: "r"(dst), "l"(src));
}
#define CP_COMMIT()   asm volatile("cp.async.commit_group;" ::: "memory")
#define CP_WAIT_1()   asm volatile("cp.async.wait_group 1;" ::: "memory")

__device__ __forceinline__ void ldsm_x4(uint32_t* r, uint32_t a) {
    asm volatile("ldmatrix.sync.aligned.m8n8.x4.shared.b16 {%0,%1,%2,%3}, [%4];"
                 : "=r"(r[0]), "=r"(r[1]), "=r"(r[2]), "=r"(r[3]) : "r"(a));
}

// fp32 -> tf32 canonical bits, round-to-nearest (unbiased)
__device__ __forceinline__ uint32_t f2tf(float x) {
    uint32_t d;
    asm("cvt.rna.tf32.f32 %0, %1;" : "=r"(d) : "f"(x));
    return d;
}

__device__ __forceinline__ void mma_tf32(float* d, const uint32_t* a, const uint32_t* b) {
    asm volatile(
        "mma.sync.aligned.m16n8k8.row.col.f32.tf32.tf32.f32 "
        "{%0,%1,%2,%3}, {%4,%5,%6,%7}, {%8,%9}, {%0,%1,%2,%3};"
        : "+f"(d[0]), "+f"(d[1]), "+f"(d[2]), "+f"(d[3])
        : "r"(a[0]), "r"(a[1]), "r"(a[2]), "r"(a[3]), "r"(b[0]), "r"(b[1]));
}

// ---------------------------------------------------------------------------
// Kernel: top-1 routing (+ optional idx tail in output)
// ---------------------------------------------------------------------------
__global__ void route_kernel(const float* __restrict__ probs,
                             float* __restrict__ out_tail, int n_tail) {
    int b = threadIdx.x;
    if (b < NB) {
        const float* p = probs + b * NE;
        float best = p[0];
        int bi = 0;
#pragma unroll
        for (int e = 1; e < NE; e++) {
            float v = p[e];
            if (v > best) { best = v; bi = e; }
        }
        g_expert_idx[b] = bi;
        if (out_tail != nullptr && b < n_tail) out_tail[b] = (float)bi;
    }
}

// ---------------------------------------------------------------------------
// Kernel: fp32 -> tf32-canonical fp32 bits (pre-rounding pass).
// ---------------------------------------------------------------------------
__global__ void tf32_round_kernel(const float4* __restrict__ src, int n4, int which) {
    int i = blockIdx.x * blockDim.x + threadIdx.x;
    if (i >= n4) return;
    uint4* dst = (uint4*)(which ? g_w_tf : g_x_tf);
    float4 v = src[i];
    uint4 o;
    o.x = f2tf(v.x);
    o.y = f2tf(v.y);
    o.z = f2tf(v.z);
    o.w = f2tf(v.w);
    dst[i] = o;
}

// ---------------------------------------------------------------------------
// TF32 GEMM, 128x128 tile, 128 threads (4 warps 2x2, warp tile 64x64),
// BK=32, 3-stage cp.async, 2 CTAs/SM to overlap barrier bubbles.
//   C[b][m][n] = x[b][m][:] . W[e(b)][n][:] + bias[e(b)][n]
// ---------------------------------------------------------------------------
#define BM 128
#define BN 128
#define BK 32
#define STAGES 3
#define ROWB 144                    // 128B row (32 fp32) + 16B pad -> conflict-free ldsm
#define A_OFF 0
#define B_OFF (128 * ROWB)          // 18432
#define STAGE_BYTES (2 * 128 * ROWB)   // 36864
#define KBLOCKS (NIN / BK)          // 32

__global__ __launch_bounds__(128, 2)
void moe_tf32_gemm(const float* __restrict__ bias_all,
                   float* __restrict__ out) {
    extern __shared__ char dyn_smem[];
    const uint32_t sbase = smem_u32(dyn_smem);

    const int tid = threadIdx.x;
    const int wid = tid >> 5;       // 0..3
    const int l   = tid & 31;
    const int warp_m = wid >> 1;    // 0..1  (64 rows each)
    const int warp_n = wid & 1;     // 0..1  (64 cols each)

    const int b = blockIdx.z;
    const int e = g_expert_idx[b];
    const int block_row = blockIdx.y * BM;
    const int block_col = blockIdx.x * BN;

    const float* __restrict__ Ag = g_x_tf + (size_t)b * NS * NIN;
    const float* __restrict__ Bg = g_w_tf + (size_t)e * NOUT * NIN;

    // cp.async: A = 1024 16B chunks, B = 1024; 128 threads -> 8 each per array
    auto load_stage = [&](int stage, int k0) {
        uint32_t sb = sbase + stage * STAGE_BYTES;
#pragma unroll
        for (int u = 0; u < 8; u++) {
            int c = tid + u * 128;
            int r = c >> 3, j = c & 7;
            uint32_t so = (uint32_t)r * ROWB + j * 16;
            cp16(sb + A_OFF + so, Ag + (size_t)(block_row + r) * NIN + k0 + j * 4);
            cp16(sb + B_OFF + so, Bg + (size_t)(block_col + r) * NIN + k0 + j * 4);
        }
        CP_COMMIT();
    };

    // Accumulators: 4 m-tiles(16) x 8 n-tiles(8) x 4 = 128 regs
    float acc[4][8][4];
#pragma unroll
    for (int i = 0; i < 4; i++)
#pragma unroll
        for (int j = 0; j < 8; j++)
#pragma unroll
            for (int q = 0; q < 4; q++) acc[i][j][q] = 0.0f;

    // ldmatrix lane-address components (fp32-as-b16 trick, same layout as R7/R8)
    const uint32_t a_lrow = (uint32_t)(l & 15);
    const uint32_t a_lb   = (uint32_t)((l >> 4) & 1) * 16;
    const uint32_t b_lrow = (uint32_t)((l & 7) + (((l >> 4) & 1) << 3));
    const uint32_t b_lb   = (uint32_t)((l >> 3) & 1) * 16;

    // Prologue: stages 0,1 in flight
    load_stage(0, 0);
    load_stage(1, BK);

    for (int kb = 0; kb < KBLOCKS; kb++) {
        CP_WAIT_1();            // stage kb complete
        __syncthreads();        // loads visible; buffer (kb+2)%3 free

        if (kb + 2 < KBLOCKS) load_stage((kb + 2) % STAGES, (kb + 2) * BK);
        else CP_COMMIT();       // keep group count uniform

        const uint32_t sb = sbase + (kb % STAGES) * STAGE_BYTES;
        const uint32_t a_base = sb + A_OFF + (warp_m * 64 + a_lrow) * ROWB + a_lb;
        const uint32_t b_base = sb + B_OFF + (warp_n * 64 + b_lrow) * ROWB + b_lb;

#pragma unroll
        for (int ks = 0; ks < 4; ks++) {        // 4 x k=8
            const uint32_t kso = ks * 32;
            uint32_t af[4][4], bf[8][2];
#pragma unroll
            for (int mt = 0; mt < 4; mt++)
                ldsm_x4(af[mt], a_base + mt * (16 * ROWB) + kso);
#pragma unroll
            for (int np = 0; np < 4; np++) {
                uint32_t t[4];
                ldsm_x4(t, b_base + np * (16 * ROWB) + kso);
                bf[2 * np + 0][0] = t[0]; bf[2 * np + 0][1] = t[1];
                bf[2 * np + 1][0] = t[2]; bf[2 * np + 1][1] = t[3];
            }
#pragma unroll
            for (int mt = 0; mt < 4; mt++)
#pragma unroll
                for (int nt = 0; nt < 8; nt++)
                    mma_tf32(acc[mt][nt], af[mt], bf[nt]);
        }
    }

    // ---- epilogue: bias + direct stores (64x64 per warp) ----
    const float* bias = bias_all + (size_t)e * NOUT;
    float* outb = out + (size_t)b * NS * NOUT;
    const int r0 = block_row + warp_m * 64 + (l >> 2);
    const int c0 = block_col + warp_n * 64 + (l & 3) * 2;

#pragma unroll
    for (int nt = 0; nt < 8; nt++) {
        int cc = c0 + nt * 8;
        float2 bb = *(const float2*)(bias + cc);
#pragma unroll
        for (int mt = 0; mt < 4; mt++) {
            int rr = r0 + mt * 16;
            float2 v0 = { acc[mt][nt][0] + bb.x, acc[mt][nt][1] + bb.y };
            float2 v1 = { acc[mt][nt][2] + bb.x, acc[mt][nt][3] + bb.y };
            *(float2*)(outb + (size_t)rr * NOUT + cc)       = v0;
            *(float2*)(outb + (size_t)(rr + 8) * NOUT + cc) = v1;
        }
    }
}

// ---------------------------------------------------------------------------
// kernel_launch
// Inputs: x [B,S,IN] f32, expert_probs [B,E] f32,
//         expert_weights [E,OUT,IN] f32, expert_biases [E,OUT] f32
// ---------------------------------------------------------------------------
extern "C" void kernel_launch(void* const* d_in, const int* in_sizes, int n_in,
                              void* d_out, int out_size) {
    const float* x     = (const float*)d_in[0];
    const float* probs = (const float*)d_in[1];
    const float* w     = (const float*)d_in[2];
    const float* bias  = (const float*)d_in[3];
    float* out = (float*)d_out;

    const long long main_elems = (long long)NB * NS * NOUT;
    long long tail_ll = (long long)out_size - main_elems;
    int n_tail = 0;
    float* out_tail = nullptr;
    if (tail_ll > 0) {
        n_tail = (int)(tail_ll < NB ? tail_ll : NB);
        out_tail = out + main_elems;
    }

    // Pre-round x and W to tf32-canonical bits (memory-bound, ~70 us)
    const int n4_x = (NB * NS * NIN) / 4;
    const int n4_w = (NE * NOUT * NIN) / 4;
    tf32_round_kernel<<<(n4_x + 255) / 256, 256>>>((const float4*)x, n4_x, 0);
    tf32_round_kernel<<<(n4_w + 255) / 256, 256>>>((const float4*)w, n4_w, 1);

    route_kernel<<<1, 32>>>(probs, out_tail, n_tail);

    const int dyn_smem = STAGES * STAGE_BYTES;   // 110,592 bytes (x2 CTAs = 216KB/SM)
    cudaFuncSetAttribute(moe_tf32_gemm, cudaFuncAttributeMaxDynamicSharedMemorySize, dyn_smem);
    dim3 grid(NOUT / BN, NS / BM, NB);           // (32, 16, 16) = 8192 CTAs
    moe_tf32_gemm<<<grid, 128, dyn_smem>>>(bias, out);
}

// round 11
// speedup vs baseline: 4.7024x; 1.1890x over previous
#include <cuda_runtime.h>
#include <cuda_bf16.h>
#include <cstdint>

// Problem constants: E=8, OUT=4096, IN=1024, B=16, S=2048
#define NB   16
#define NS   2048
#define NIN  1024
#define NOUT 4096
#define NE   8

// Device scratch (no allocations allowed): routing + tf32-rounded copies.
__device__ int g_expert_idx[NB];
__device__ float g_x_tf[(size_t)NB * NS * NIN];     // 128 MB
__device__ float g_w_tf[(size_t)NE * NOUT * NIN];   // 128 MB

// ---------------------------------------------------------------------------
// PTX helpers (target-neutral: cp.async / ldmatrix / mma.sync tf32)
// ---------------------------------------------------------------------------
__device__ __forceinline__ uint32_t smem_u32(const void* p) {
    uint32_t a;
    asm("{ .reg .u64 t; cvta.to.shared.u64 t, %1; cvt.u32.u64 %0, t; }"
        : "=r"(a) : "l"(p));
    return a;
}

__device__ __forceinline__ void cp16(uint32_t dst, const void* src) {
    asm volatile("cp.async.cg.shared.global [%0], [%1], 16;" :: "r"(dst), "l"(src));
}
#define CP_COMMIT()   asm volatile("cp.async.commit_group;" ::: "memory")
#define CP_WAIT_1()   asm volatile("cp.async.wait_group 1;" ::: "memory")

__device__ __forceinline__ void ldsm_x4(uint32_t* r, uint32_t a) {
    asm volatile("ldmatrix.sync.aligned.m8n8.x4.shared.b16 {%0,%1,%2,%3}, [%4];"
                 : "=r"(r[0]), "=r"(r[1]), "=r"(r[2]), "=r"(r[3]) : "r"(a));
}

// fp32 -> tf32 canonical bits, round-to-nearest (unbiased)
__device__ __forceinline__ uint32_t f2tf(float x) {
    uint32_t d;
    asm("cvt.rna.tf32.f32 %0, %1;" : "=r"(d) : "f"(x));
    return d;
}

__device__ __forceinline__ void mma_tf32(float* d, const uint32_t* a, const uint32_t* b) {
    asm volatile(
        "mma.sync.aligned.m16n8k8.row.col.f32.tf32.tf32.f32 "
        "{%0,%1,%2,%3}, {%4,%5,%6,%7}, {%8,%9}, {%0,%1,%2,%3};"
        : "+f"(d[0]), "+f"(d[1]), "+f"(d[2]), "+f"(d[3])
        : "r"(a[0]), "r"(a[1]), "r"(a[2]), "r"(a[3]), "r"(b[0]), "r"(b[1]));
}

// ---------------------------------------------------------------------------
// Kernel: top-1 routing (+ optional idx tail in output)
// ---------------------------------------------------------------------------
__global__ void route_kernel(const float* __restrict__ probs,
                             float* __restrict__ out_tail, int n_tail) {
    int b = threadIdx.x;
    if (b < NB) {
        const float* p = probs + b * NE;
        float best = p[0];
        int bi = 0;
#pragma unroll
        for (int e = 1; e < NE; e++) {
            float v = p[e];
            if (v > best) { best = v; bi = e; }
        }
        g_expert_idx[b] = bi;
        if (out_tail != nullptr && b < n_tail) out_tail[b] = (float)bi;
    }
}

// ---------------------------------------------------------------------------
// Kernel: fp32 -> tf32-canonical fp32 bits (pre-rounding pass).
// ---------------------------------------------------------------------------
__global__ void tf32_round_kernel(const float4* __restrict__ src, int n4, int which) {
    int i = blockIdx.x * blockDim.x + threadIdx.x;
    if (i >= n4) return;
    uint4* dst = (uint4*)(which ? g_w_tf : g_x_tf);
    float4 v = src[i];
    uint4 o;
    o.x = f2tf(v.x);
    o.y = f2tf(v.y);
    o.z = f2tf(v.z);
    o.w = f2tf(v.w);
    dst[i] = o;
}

// ---------------------------------------------------------------------------
// TF32 GEMM, 128x128 tile, 128 threads (4 warps 2x2, warp tile 64x64),
// BK=32, 3-stage cp.async, XOR-swizzled smem (no padding), fragment
// double-buffering, 2 CTAs/SM.
//   C[b][m][n] = x[b][m][:] . W[e(b)][n][:] + bias[e(b)][n]
// ---------------------------------------------------------------------------
#define BM 128
#define BN 128
#define BK 32
#define STAGES 3
// Row = 128B (32 fp32) = 8 chunks of 16B; swizzled chunk = j ^ (row & 7).
#define A_OFF 0
#define B_OFF 16384
#define STAGE_BYTES 32768
#define KBLOCKS (NIN / BK)          // 32

__global__ __launch_bounds__(128, 2)
void moe_tf32_gemm(const float* __restrict__ bias_all,
                   float* __restrict__ out) {
    extern __shared__ char dyn_smem[];
    const uint32_t sbase = smem_u32(dyn_smem);

    const int tid = threadIdx.x;
    const int wid = tid >> 5;       // 0..3
    const int l   = tid & 31;
    const int warp_m = wid >> 1;    // 0..1  (64 rows each)
    const int warp_n = wid & 1;     // 0..1  (64 cols each)

    const int b = blockIdx.z;
    const int e = g_expert_idx[b];
    const int block_row = blockIdx.y * BM;
    const int block_col = blockIdx.x * BN;

    const float* __restrict__ Ag = g_x_tf + (size_t)b * NS * NIN;
    const float* __restrict__ Bg = g_w_tf + (size_t)e * NOUT * NIN;

    // cp.async: A = 1024 16B chunks, B = 1024; 128 threads -> 8 each per array.
    // Swizzled store: chunk j of row r goes to chunk (j ^ (r&7)).
    auto load_stage = [&](int stage, int k0) {
        uint32_t sb = sbase + stage * STAGE_BYTES;
#pragma unroll
        for (int u = 0; u < 8; u++) {
            int c = tid + u * 128;
            int r = c >> 3, j = c & 7;
            uint32_t so = ((uint32_t)r << 7) + (uint32_t)((j ^ (r & 7)) << 4);
            cp16(sb + A_OFF + so, Ag + (size_t)(block_row + r) * NIN + k0 + j * 4);
            cp16(sb + B_OFF + so, Bg + (size_t)(block_col + r) * NIN + k0 + j * 4);
        }
        CP_COMMIT();
    };

    // Accumulators: 4 m-tiles(16) x 8 n-tiles(8) x 4 = 128 regs
    float acc[4][8][4];
#pragma unroll
    for (int i = 0; i < 4; i++)
#pragma unroll
        for (int j = 0; j < 8; j++)
#pragma unroll
            for (int q = 0; q < 4; q++) acc[i][j][q] = 0.0f;

    // ldsm lane addressing (swizzled).  For both A and B lane rows satisfy
    // row&7 == l&7, so the swizzle is chunk ^ (l&7) — constant per lane.
    const uint32_t lx    = (uint32_t)(l & 7);
    const uint32_t a_row = (uint32_t)(warp_m * 64 + (l & 15));           // + mt*16
    const uint32_t a_hi  = (uint32_t)((l >> 4) & 1);                     // chunk lsb
    const uint32_t b_row = (uint32_t)(warp_n * 64 + (l & 7) + (((l >> 4) & 1) << 3)); // + np*16
    const uint32_t b_hi  = (uint32_t)((l >> 3) & 1);

    // Fragment buffers (double-buffered across k-steps)
    uint32_t af[2][4][4], bf[2][8][2];

    auto ld_frags = [&](uint32_t sb, int ks, int buf) {
        const uint32_t ac = (uint32_t)(2 * ks) + a_hi;
        const uint32_t bc = (uint32_t)(2 * ks) + b_hi;
        const uint32_t a_base = sb + A_OFF + (a_row << 7) + ((ac ^ lx) << 4);
        const uint32_t b_base = sb + B_OFF + (b_row << 7) + ((bc ^ lx) << 4);
#pragma unroll
        for (int mt = 0; mt < 4; mt++)
            ldsm_x4(af[buf][mt], a_base + mt * (16 << 7));
#pragma unroll
        for (int np = 0; np < 4; np++) {
            uint32_t t[4];
            ldsm_x4(t, b_base + np * (16 << 7));
            bf[buf][2 * np + 0][0] = t[0]; bf[buf][2 * np + 0][1] = t[1];
            bf[buf][2 * np + 1][0] = t[2]; bf[buf][2 * np + 1][1] = t[3];
        }
    };

    // Prologue: stages 0,1 in flight
    load_stage(0, 0);
    load_stage(1, BK);

    for (int kb = 0; kb < KBLOCKS; kb++) {
        CP_WAIT_1();            // stage kb complete
        __syncthreads();        // loads visible; buffer (kb+2)%3 free

        if (kb + 2 < KBLOCKS) load_stage((kb + 2) % STAGES, (kb + 2) * BK);
        else CP_COMMIT();       // keep group count uniform

        const uint32_t sb = sbase + (kb % STAGES) * STAGE_BYTES;

        ld_frags(sb, 0, 0);
#pragma unroll
        for (int ks = 0; ks < 4; ks++) {
            const int cur = ks & 1;
            if (ks < 3) ld_frags(sb, ks + 1, cur ^ 1);   // prefetch next k-step
#pragma unroll
            for (int mt = 0; mt < 4; mt++)
#pragma unroll
                for (int nt = 0; nt < 8; nt++)
                    mma_tf32(acc[mt][nt], af[cur][mt], bf[cur][nt]);
        }
    }

    // ---- epilogue: bias + direct stores (64x64 per warp) ----
    const float* bias = bias_all + (size_t)e * NOUT;
    float* outb = out + (size_t)b * NS * NOUT;
    const int r0 = block_row + warp_m * 64 + (l >> 2);
    const int c0 = block_col + warp_n * 64 + (l & 3) * 2;

#pragma unroll
    for (int nt = 0; nt < 8; nt++) {
        int cc = c0 + nt * 8;
        float2 bb = *(const float2*)(bias + cc);
#pragma unroll
        for (int mt = 0; mt < 4; mt++) {
            int rr = r0 + mt * 16;
            float2 v0 = { acc[mt][nt][0] + bb.x, acc[mt][nt][1] + bb.y };
            float2 v1 = { acc[mt][nt][2] + bb.x, acc[mt][nt][3] + bb.y };
            *(float2*)(outb + (size_t)rr * NOUT + cc)       = v0;
            *(float2*)(outb + (size_t)(rr + 8) * NOUT + cc) = v1;
        }
    }
}

// ---------------------------------------------------------------------------
// kernel_launch
// Inputs: x [B,S,IN] f32, expert_probs [B,E] f32,
//         expert_weights [E,OUT,IN] f32, expert_biases [E,OUT] f32
// ---------------------------------------------------------------------------
extern "C" void kernel_launch(void* const* d_in, const int* in_sizes, int n_in,
                              void* d_out, int out_size) {
    const float* x     = (const float*)d_in[0];
    const float* probs = (const float*)d_in[1];
    const float* w     = (const float*)d_in[2];
    const float* bias  = (const float*)d_in[3];
    float* out = (float*)d_out;

    const long long main_elems = (long long)NB * NS * NOUT;
    long long tail_ll = (long long)out_size - main_elems;
    int n_tail = 0;
    float* out_tail = nullptr;
    if (tail_ll > 0) {
        n_tail = (int)(tail_ll < NB ? tail_ll : NB);
        out_tail = out + main_elems;
    }

    // Pre-round x and W to tf32-canonical bits (memory-bound, ~70 us)
    const int n4_x = (NB * NS * NIN) / 4;
    const int n4_w = (NE * NOUT * NIN) / 4;
    tf32_round_kernel<<<(n4_x + 255) / 256, 256>>>((const float4*)x, n4_x, 0);
    tf32_round_kernel<<<(n4_w + 255) / 256, 256>>>((const float4*)w, n4_w, 1);

    route_kernel<<<1, 32>>>(probs, out_tail, n_tail);

    const int dyn_smem = STAGES * STAGE_BYTES;   // 98,304 bytes (x2 CTAs = 192KB/SM)
    cudaFuncSetAttribute(moe_tf32_gemm, cudaFuncAttributeMaxDynamicSharedMemorySize, dyn_smem);
    dim3 grid(NOUT / BN, NS / BM, NB);           // (32, 16, 16) = 8192 CTAs
    moe_tf32_gemm<<<grid, 128, dyn_smem>>>(bias, out);
}

// round 12
// speedup vs baseline: 8.5375x; 1.8156x over previous
#include <cuda_runtime.h>
#include <cuda_fp16.h>
#include <cstdint>

// Problem constants: E=8, OUT=4096, IN=1024, B=16, S=2048
#define NB   16
#define NS   2048
#define NIN  1024
#define NOUT 4096
#define NE   8

// Device scratch (no allocations allowed): routing + fp16 copies.
__device__ int g_expert_idx[NB];
__device__ __half g_x_h[(size_t)NB * NS * NIN];     // 64 MB
__device__ __half g_w_h[(size_t)NE * NOUT * NIN];   // 64 MB

// ---------------------------------------------------------------------------
// PTX helpers (target-neutral: cp.async / ldmatrix / mma.sync fp16)
// ---------------------------------------------------------------------------
__device__ __forceinline__ uint32_t smem_u32(const void* p) {
    uint32_t a;
    asm("{ .reg .u64 t; cvta.to.shared.u64 t, %1; cvt.u32.u64 %0, t; }"
        : "=r"(a) : "l"(p));
    return a;
}

__device__ __forceinline__ void cp16(uint32_t dst, const void* src) {
    asm volatile("cp.async.cg.shared.global [%0], [%1], 16;" :: "r"(dst), "l"(src));
}
#define CP_COMMIT()   asm volatile("cp.async.commit_group;" ::: "memory")
#define CP_WAIT_1()   asm volatile("cp.async.wait_group 1;" ::: "memory")

__device__ __forceinline__ void ldsm_x4(uint32_t* r, uint32_t a) {
    asm volatile("ldmatrix.sync.aligned.m8n8.x4.shared.b16 {%0,%1,%2,%3}, [%4];"
                 : "=r"(r[0]), "=r"(r[1]), "=r"(r[2]), "=r"(r[3]) : "r"(a));
}

// fp16 MMA, fp32 accumulate: m16n8k16 (2x the FLOPs/inst of tf32 m16n8k8,
// same 11-bit mantissa precision).
__device__ __forceinline__ void mma_f16(float* d, const uint32_t* a, const uint32_t* b) {
    asm volatile(
        "mma.sync.aligned.m16n8k16.row.col.f32.f16.f16.f32 "
        "{%0,%1,%2,%3}, {%4,%5,%6,%7}, {%8,%9}, {%0,%1,%2,%3};"
        : "+f"(d[0]), "+f"(d[1]), "+f"(d[2]), "+f"(d[3])
        : "r"(a[0]), "r"(a[1]), "r"(a[2]), "r"(a[3]), "r"(b[0]), "r"(b[1]));
}

// ---------------------------------------------------------------------------
// Kernel: top-1 routing (+ optional idx tail in output)
// ---------------------------------------------------------------------------
__global__ void route_kernel(const float* __restrict__ probs,
                             float* __restrict__ out_tail, int n_tail) {
    int b = threadIdx.x;
    if (b < NB) {
        const float* p = probs + b * NE;
        float best = p[0];
        int bi = 0;
#pragma unroll
        for (int e = 1; e < NE; e++) {
            float v = p[e];
            if (v > best) { best = v; bi = e; }
        }
        g_expert_idx[b] = bi;
        if (out_tail != nullptr && b < n_tail) out_tail[b] = (float)bi;
    }
}

// ---------------------------------------------------------------------------
// Kernel: fp32 -> fp16 conversion pre-pass (RN, unbiased).
// which=0 -> g_x_h, 1 -> g_w_h.
// ---------------------------------------------------------------------------
__global__ void f16_convert_kernel(const float4* __restrict__ src, int n4, int which) {
    int i = blockIdx.x * blockDim.x + threadIdx.x;
    if (i >= n4) return;
    __half2* dst = (__half2*)(which ? g_w_h : g_x_h);
    float4 v = src[i];
    dst[2 * i + 0] = __floats2half2_rn(v.x, v.y);
    dst[2 * i + 1] = __floats2half2_rn(v.z, v.w);
}

// ---------------------------------------------------------------------------
// FP16 GEMM (fp32 accumulate), 128x128 tile, 128 threads (4 warps 2x2,
// warp tile 64x64), BK=64 fp16, 3-stage cp.async, XOR-swizzled smem,
// fragment double-buffering, 2 CTAs/SM.
//   C[b][m][n] = x[b][m][:] . W[e(b)][n][:] + bias[e(b)][n]
// ---------------------------------------------------------------------------
#define BM 128
#define BN 128
#define BK 64                       // fp16 elements -> 128B row, 8 x 16B chunks
#define STAGES 3
#define A_OFF 0
#define B_OFF 16384
#define STAGE_BYTES 32768
#define KBLOCKS (NIN / BK)          // 16

__global__ __launch_bounds__(128, 2)
void moe_f16_gemm(const float* __restrict__ bias_all,
                  float* __restrict__ out) {
    extern __shared__ char dyn_smem[];
    const uint32_t sbase = smem_u32(dyn_smem);

    const int tid = threadIdx.x;
    const int wid = tid >> 5;       // 0..3
    const int l   = tid & 31;
    const int warp_m = wid >> 1;    // 0..1  (64 rows each)
    const int warp_n = wid & 1;     // 0..1  (64 cols each)

    const int b = blockIdx.z;
    const int e = g_expert_idx[b];
    const int block_row = blockIdx.y * BM;
    const int block_col = blockIdx.x * BN;

    const __half* __restrict__ Ag = g_x_h + (size_t)b * NS * NIN;
    const __half* __restrict__ Bg = g_w_h + (size_t)e * NOUT * NIN;

    // cp.async: A = 1024 16B chunks, B = 1024; 128 threads -> 8 each per array.
    // Swizzled store: chunk j of row r goes to chunk (j ^ (r&7)).
    auto load_stage = [&](int stage, int k0) {
        uint32_t sb = sbase + stage * STAGE_BYTES;
#pragma unroll
        for (int u = 0; u < 8; u++) {
            int c = tid + u * 128;
            int r = c >> 3, j = c & 7;
            uint32_t so = ((uint32_t)r << 7) + (uint32_t)((j ^ (r & 7)) << 4);
            cp16(sb + A_OFF + so, Ag + (size_t)(block_row + r) * NIN + k0 + j * 8);
            cp16(sb + B_OFF + so, Bg + (size_t)(block_col + r) * NIN + k0 + j * 8);
        }
        CP_COMMIT();
    };

    // Accumulators: 4 m-tiles(16) x 8 n-tiles(8) x 4 = 128 regs
    float acc[4][8][4];
#pragma unroll
    for (int i = 0; i < 4; i++)
#pragma unroll
        for (int j = 0; j < 8; j++)
#pragma unroll
            for (int q = 0; q < 4; q++) acc[i][j][q] = 0.0f;

    // ldsm lane addressing (swizzled).  Lane rows satisfy row&7 == l&7, so the
    // swizzle is chunk ^ (l&7) — constant per lane.  One 16B chunk = 8 fp16 = k8.
    const uint32_t lx    = (uint32_t)(l & 7);
    const uint32_t a_row = (uint32_t)(warp_m * 64 + (l & 15));           // + mt*16
    const uint32_t a_hi  = (uint32_t)((l >> 4) & 1);                     // k8-half
    const uint32_t b_row = (uint32_t)(warp_n * 64 + (l & 7) + (((l >> 4) & 1) << 3)); // + np*16
    const uint32_t b_hi  = (uint32_t)((l >> 3) & 1);

    // Fragment buffers (double-buffered across k16-steps)
    uint32_t af[2][4][4], bf[2][8][2];

    auto ld_frags = [&](uint32_t sb, int ks, int buf) {
        const uint32_t ac = (uint32_t)(2 * ks) + a_hi;   // 2 chunks per k16-step
        const uint32_t bc = (uint32_t)(2 * ks) + b_hi;
        const uint32_t a_base = sb + A_OFF + (a_row << 7) + ((ac ^ lx) << 4);
        const uint32_t b_base = sb + B_OFF + (b_row << 7) + ((bc ^ lx) << 4);
#pragma unroll
        for (int mt = 0; mt < 4; mt++)
            ldsm_x4(af[buf][mt], a_base + mt * (16 << 7));
#pragma unroll
        for (int np = 0; np < 4; np++) {
            uint32_t t[4];
            ldsm_x4(t, b_base + np * (16 << 7));
            bf[buf][2 * np + 0][0] = t[0]; bf[buf][2 * np + 0][1] = t[1];
            bf[buf][2 * np + 1][0] = t[2]; bf[buf][2 * np + 1][1] = t[3];
        }
    };

    // Prologue: stages 0,1 in flight
    load_stage(0, 0);
    load_stage(1, BK);

    for (int kb = 0; kb < KBLOCKS; kb++) {
        CP_WAIT_1();            // stage kb complete
        __syncthreads();        // loads visible; buffer (kb+2)%3 free

        if (kb + 2 < KBLOCKS) load_stage((kb + 2) % STAGES, (kb + 2) * BK);
        else CP_COMMIT();       // keep group count uniform

        const uint32_t sb = sbase + (kb % STAGES) * STAGE_BYTES;

        ld_frags(sb, 0, 0);
#pragma unroll
        for (int ks = 0; ks < 4; ks++) {        // 4 x k16
            const int cur = ks & 1;
            if (ks < 3) ld_frags(sb, ks + 1, cur ^ 1);   // prefetch next k-step
#pragma unroll
            for (int mt = 0; mt < 4; mt++)
#pragma unroll
                for (int nt = 0; nt < 8; nt++)
                    mma_f16(acc[mt][nt], af[cur][mt], bf[cur][nt]);
        }
    }

    // ---- epilogue: bias + direct stores (64x64 per warp) ----
    const float* bias = bias_all + (size_t)e * NOUT;
    float* outb = out + (size_t)b * NS * NOUT;
    const int r0 = block_row + warp_m * 64 + (l >> 2);
    const int c0 = block_col + warp_n * 64 + (l & 3) * 2;

#pragma unroll
    for (int nt = 0; nt < 8; nt++) {
        int cc = c0 + nt * 8;
        float2 bb = *(const float2*)(bias + cc);
#pragma unroll
        for (int mt = 0; mt < 4; mt++) {
            int rr = r0 + mt * 16;
            float2 v0 = { acc[mt][nt][0] + bb.x, acc[mt][nt][1] + bb.y };
            float2 v1 = { acc[mt][nt][2] + bb.x, acc[mt][nt][3] + bb.y };
            *(float2*)(outb + (size_t)rr * NOUT + cc)       = v0;
            *(float2*)(outb + (size_t)(rr + 8) * NOUT + cc) = v1;
        }
    }
}

// ---------------------------------------------------------------------------
// kernel_launch
// Inputs: x [B,S,IN] f32, expert_probs [B,E] f32,
//         expert_weights [E,OUT,IN] f32, expert_biases [E,OUT] f32
// ---------------------------------------------------------------------------
extern "C" void kernel_launch(void* const* d_in, const int* in_sizes, int n_in,
                              void* d_out, int out_size) {
    const float* x     = (const float*)d_in[0];
    const float* probs = (const float*)d_in[1];
    const float* w     = (const float*)d_in[2];
    const float* bias  = (const float*)d_in[3];
    float* out = (float*)d_out;

    const long long main_elems = (long long)NB * NS * NOUT;
    long long tail_ll = (long long)out_size - main_elems;
    int n_tail = 0;
    float* out_tail = nullptr;
    if (tail_ll > 0) {
        n_tail = (int)(tail_ll < NB ? tail_ll : NB);
        out_tail = out + main_elems;
    }

    // Convert x and W to fp16 (memory-bound, ~55 us)
    const int n4_x = (NB * NS * NIN) / 4;
    const int n4_w = (NE * NOUT * NIN) / 4;
    f16_convert_kernel<<<(n4_x + 255) / 256, 256>>>((const float4*)x, n4_x, 0);
    f16_convert_kernel<<<(n4_w + 255) / 256, 256>>>((const float4*)w, n4_w, 1);

    route_kernel<<<1, 32>>>(probs, out_tail, n_tail);

    const int dyn_smem = STAGES * STAGE_BYTES;   // 98,304 bytes (x2 CTAs = 192KB/SM)
    cudaFuncSetAttribute(moe_f16_gemm, cudaFuncAttributeMaxDynamicSharedMemorySize, dyn_smem);
    dim3 grid(NOUT / BN, NS / BM, NB);           // (32, 16, 16) = 8192 CTAs
    moe_f16_gemm<<<grid, 128, dyn_smem>>>(bias, out);
}